// round 1
// baseline (speedup 1.0000x reference)
#include <cuda_runtime.h>
#include <math.h>

#define B   2
#define S   4096
#define D   2048
#define HQ  16
#define HKV 4
#define HD  128
#define W   512
#define BS  (B*S)           // 8192
#define REP (HQ/HKV)        // 4

// ---------------- scratch (device globals; no allocation allowed) ----------
__device__ float g_xn [ (size_t)BS * D ];          // rmsnorm output        64MB
__device__ float g_qp [ (size_t)BS * HQ * HD ];    // q proj pre-rope       64MB
__device__ float g_kp [ (size_t)BS * HKV * HD ];   // k proj pre-rope       16MB
__device__ float g_vp [ (size_t)BS * HKV * HD ];   // v proj                16MB
__device__ float g_q  [ (size_t)BS * HQ * HD ];    // [B,HQ,S,HD]           64MB
__device__ float g_k  [ (size_t)BS * HKV * HD ];   // [B,HKV,S,HD]          16MB
__device__ float g_v  [ (size_t)BS * HKV * HD ];   // [B,HKV,S,HD]          16MB
__device__ float g_att[ (size_t)BS * D ];          // attention out [B,S,D] 64MB
__device__ float g_cos[ S * (HD/2) ];
__device__ float g_sin[ S * (HD/2) ];

// ---------------- packed f32x2 helpers (sm_103a) ---------------------------
__device__ __forceinline__ unsigned long long pack2(float x, float y) {
    unsigned long long r;
    asm("mov.b64 %0, {%1, %2};" : "=l"(r) : "f"(x), "f"(y));
    return r;
}
__device__ __forceinline__ unsigned long long ffma2u(unsigned long long a,
                                                     unsigned long long b,
                                                     unsigned long long c) {
    unsigned long long d;
    asm("fma.rn.f32x2 %0, %1, %2, %3;" : "=l"(d) : "l"(a), "l"(b), "l"(c));
    return d;
}
__device__ __forceinline__ float2 unpack2(unsigned long long v) {
    float2 r;
    asm("mov.b64 {%0, %1}, %2;" : "=f"(r.x), "=f"(r.y) : "l"(v));
    return r;
}

// ---------------- RoPE tables in fp64 --------------------------------------
__global__ void rope_table_kernel() {
    int pos = blockIdx.x;
    int i   = threadIdx.x;                 // 0..63
    double inv = pow(10000.0, -(double)i / 64.0);   // 10000^(-2i/128)
    double f   = (double)pos * inv;
    g_cos[pos * 64 + i] = (float)cos(f);
    g_sin[pos * 64 + i] = (float)sin(f);
}

// ---------------- RMSNorm ---------------------------------------------------
__global__ void rmsnorm_kernel(const float* __restrict__ x,
                               const float* __restrict__ g) {
    int row = blockIdx.x;                  // 0..BS-1
    int tid = threadIdx.x;                 // 256 threads
    const float4* xr = (const float4*)(x + (size_t)row * D);
    float4 v0 = xr[tid];
    float4 v1 = xr[tid + 256];
    float ss = v0.x*v0.x + v0.y*v0.y + v0.z*v0.z + v0.w*v0.w
             + v1.x*v1.x + v1.y*v1.y + v1.z*v1.z + v1.w*v1.w;
    #pragma unroll
    for (int o = 16; o; o >>= 1) ss += __shfl_xor_sync(0xffffffffu, ss, o);
    __shared__ float red[8];
    __shared__ float s_inv;
    if ((tid & 31) == 0) red[tid >> 5] = ss;
    __syncthreads();
    if (tid == 0) {
        float t = 0.f;
        #pragma unroll
        for (int i = 0; i < 8; i++) t += red[i];
        s_inv = 1.0f / sqrtf(t / (float)D + 1e-6f);
    }
    __syncthreads();
    float inv = s_inv;
    const float4* gg = (const float4*)g;
    float4* out = (float4*)(g_xn + (size_t)row * D);
    float4 g0 = gg[tid], g1 = gg[tid + 256];
    float4 o0, o1;
    o0.x = v0.x*inv*g0.x; o0.y = v0.y*inv*g0.y; o0.z = v0.z*inv*g0.z; o0.w = v0.w*inv*g0.w;
    o1.x = v1.x*inv*g1.x; o1.y = v1.y*inv*g1.y; o1.z = v1.z*inv*g1.z; o1.w = v1.w*inv*g1.w;
    out[tid]       = o0;
    out[tid + 256] = o1;
}

// ---------------- fp32 SGEMM, 128x128x8 tiles, f32x2 inner -----------------
__global__ void __launch_bounds__(256)
sgemm_kernel(const float* __restrict__ A, const float* __restrict__ Bm,
             float* __restrict__ C, int M, int N, int K) {
    __shared__ float As[8][128];
    __shared__ float Bs[8][128];
    int tid  = threadIdx.x;
    int tx   = tid & 15;            // N direction (x8)
    int ty   = tid >> 4;            // M direction (x8)
    int row0 = blockIdx.y * 128;
    int col0 = blockIdx.x * 128;
    int arow = tid >> 1, acol = (tid & 1) << 2;
    int brow = tid >> 5, bcol = (tid & 31) << 2;
    const float* Ap = A  + (size_t)(row0 + arow) * K + acol;
    const float* Bp = Bm + (size_t)brow * N + col0 + bcol;

    unsigned long long acc[8][4];
    #pragma unroll
    for (int i = 0; i < 8; i++)
        #pragma unroll
        for (int j = 0; j < 4; j++) acc[i][j] = 0ull;

    for (int k0 = 0; k0 < K; k0 += 8) {
        float4 av = *(const float4*)(Ap + k0);
        As[acol + 0][arow] = av.x;
        As[acol + 1][arow] = av.y;
        As[acol + 2][arow] = av.z;
        As[acol + 3][arow] = av.w;
        *(float4*)&Bs[brow][bcol] = *(const float4*)(Bp + (size_t)k0 * N);
        __syncthreads();
        #pragma unroll
        for (int kk = 0; kk < 8; kk++) {
            float a0[8];
            *(float4*)(a0)     = *(const float4*)&As[kk][ty * 8];
            *(float4*)(a0 + 4) = *(const float4*)&As[kk][ty * 8 + 4];
            unsigned long long bu[4];
            bu[0] = *(const unsigned long long*)&Bs[kk][tx * 8 + 0];
            bu[1] = *(const unsigned long long*)&Bs[kk][tx * 8 + 2];
            bu[2] = *(const unsigned long long*)&Bs[kk][tx * 8 + 4];
            bu[3] = *(const unsigned long long*)&Bs[kk][tx * 8 + 6];
            #pragma unroll
            for (int i = 0; i < 8; i++) {
                unsigned long long aii = pack2(a0[i], a0[i]);
                #pragma unroll
                for (int j = 0; j < 4; j++)
                    acc[i][j] = ffma2u(aii, bu[j], acc[i][j]);
            }
        }
        __syncthreads();
    }
    #pragma unroll
    for (int i = 0; i < 8; i++) {
        float2 c0 = unpack2(acc[i][0]);
        float2 c1 = unpack2(acc[i][1]);
        float2 c2 = unpack2(acc[i][2]);
        float2 c3 = unpack2(acc[i][3]);
        float* Cp = C + (size_t)(row0 + ty * 8 + i) * N + col0 + tx * 8;
        *(float4*)(Cp)     = make_float4(c0.x, c0.y, c1.x, c1.y);
        *(float4*)(Cp + 4) = make_float4(c2.x, c2.y, c3.x, c3.y);
    }
}

// ---------------- RoPE + transpose ------------------------------------------
__global__ void rope_q_kernel() {
    int bs = blockIdx.x;                    // b*S+s
    int b  = bs / S, s = bs % S;
    for (int p = threadIdx.x; p < HQ * 64; p += 256) {
        int h = p >> 6, i = p & 63;
        float c  = g_cos[s * 64 + i];
        float sn = g_sin[s * 64 + i];
        float2 v = *(const float2*)(g_qp + (((size_t)bs * HQ + h) * HD) + 2 * i);
        float2 o;
        o.x = v.x * c - v.y * sn;
        o.y = v.x * sn + v.y * c;
        *(float2*)(g_q + ((((size_t)b * HQ + h) * S + s) * HD) + 2 * i) = o;
    }
}
__global__ void rope_k_kernel() {
    int bs = blockIdx.x;
    int b  = bs / S, s = bs % S;
    int p  = threadIdx.x;                   // 256 = HKV*64
    int h = p >> 6, i = p & 63;
    float c  = g_cos[s * 64 + i];
    float sn = g_sin[s * 64 + i];
    float2 v = *(const float2*)(g_kp + (((size_t)bs * HKV + h) * HD) + 2 * i);
    float2 o;
    o.x = v.x * c - v.y * sn;
    o.y = v.x * sn + v.y * c;
    *(float2*)(g_k + ((((size_t)b * HKV + h) * S + s) * HD) + 2 * i) = o;
}
__global__ void vtrans_kernel() {
    int bs = blockIdx.x;
    int b  = bs / S, s = bs % S;
    int t  = threadIdx.x;                   // 128 threads
    int h  = t >> 5, c4 = t & 31;
    float4 v = *(const float4*)(g_vp + (((size_t)bs * HKV + h) * HD) + c4 * 4);
    *(float4*)(g_v + ((((size_t)b * HKV + h) * S + s) * HD) + c4 * 4) = v;
}

// ---------------- sliding-window attention ----------------------------------
#define QT 64
#define KT 32
#define PSTR 132   // padded row stride (floats): conflict-free LDS.128

__global__ void __launch_bounds__(256)
attn_kernel() {
    extern __shared__ float sm[];
    float* Qs = sm;                         // QT * PSTR
    float* Ks = sm + QT * PSTR;             // KT * PSTR
    float* Vs = Ks + KT * PSTR;             // KT * PSTR
    int qb = blockIdx.x;
    int bh = blockIdx.y;
    int b  = bh / HQ, h = bh % HQ;
    int hk = h / REP;
    int qstart = qb * QT;
    int tid = threadIdx.x, warp = tid >> 5, lane = tid & 31;
    const float scale = 0.08838834764831843f;   // 1/sqrt(128)

    const float* Qg = g_q + ((size_t)(b * HQ + h) * S + qstart) * HD;
    for (int i = tid; i < QT * 32; i += 256) {
        int r = i >> 5, c4 = i & 31;
        float4 v = *(const float4*)(Qg + (size_t)r * HD + c4 * 4);
        v.x *= scale; v.y *= scale; v.z *= scale; v.w *= scale;
        *(float4*)(Qs + r * PSTR + c4 * 4) = v;
    }

    float  mrow[8], lrow[8];
    float4 orow[8];
    #pragma unroll
    for (int rr = 0; rr < 8; rr++) {
        mrow[rr] = -1e30f; lrow[rr] = 0.f;
        orow[rr] = make_float4(0.f, 0.f, 0.f, 0.f);
    }

    int kbeg = qstart - W; if (kbeg < 0) kbeg = 0;
    int kend = qstart + QT;
    const float* Kg = g_k + ((size_t)(b * HKV + hk) * S) * HD;
    const float* Vg = g_v + ((size_t)(b * HKV + hk) * S) * HD;

    for (int ks = kbeg; ks < kend; ks += KT) {
        __syncthreads();
        for (int i = tid; i < KT * 32; i += 256) {
            int r = i >> 5, c4 = i & 31;
            *(float4*)(Ks + r * PSTR + c4 * 4) =
                *(const float4*)(Kg + (size_t)(ks + r) * HD + c4 * 4);
            *(float4*)(Vs + r * PSTR + c4 * 4) =
                *(const float4*)(Vg + (size_t)(ks + r) * HD + c4 * 4);
        }
        __syncthreads();

        #pragma unroll
        for (int rr = 0; rr < 8; rr++) {
            int r    = warp * 8 + rr;
            int qpos = qstart + r;
            int kp   = ks + lane;
            bool valid = (kp >= qpos - W) && (kp <= qpos);

            float s = 0.f;
            const float4* q4 = (const float4*)(Qs + r * PSTR);
            const float4* k4 = (const float4*)(Ks + lane * PSTR);
            #pragma unroll
            for (int c = 0; c < 32; c++) {
                float4 qa = q4[c], kb = k4[c];
                s = fmaf(qa.x, kb.x, s); s = fmaf(qa.y, kb.y, s);
                s = fmaf(qa.z, kb.z, s); s = fmaf(qa.w, kb.w, s);
            }
            s = valid ? s : -1e30f;

            float mx = s;
            #pragma unroll
            for (int o = 16; o; o >>= 1)
                mx = fmaxf(mx, __shfl_xor_sync(0xffffffffu, mx, o));
            float mnew  = fmaxf(mrow[rr], mx);
            float p     = valid ? __expf(s - mnew) : 0.f;
            float alpha = __expf(mrow[rr] - mnew);
            mrow[rr] = mnew;

            float ps = p;
            #pragma unroll
            for (int o = 16; o; o >>= 1)
                ps += __shfl_xor_sync(0xffffffffu, ps, o);
            lrow[rr] = lrow[rr] * alpha + ps;

            float4 o4 = orow[rr];
            o4.x *= alpha; o4.y *= alpha; o4.z *= alpha; o4.w *= alpha;
            #pragma unroll
            for (int kk = 0; kk < 32; kk++) {
                float pv = __shfl_sync(0xffffffffu, p, kk);
                float4 vv = *(const float4*)(Vs + kk * PSTR + lane * 4);
                o4.x = fmaf(pv, vv.x, o4.x); o4.y = fmaf(pv, vv.y, o4.y);
                o4.z = fmaf(pv, vv.z, o4.z); o4.w = fmaf(pv, vv.w, o4.w);
            }
            orow[rr] = o4;
        }
    }

    #pragma unroll
    for (int rr = 0; rr < 8; rr++) {
        int qpos = qstart + warp * 8 + rr;
        float inv = 1.f / lrow[rr];
        float4 o4 = orow[rr];
        o4.x *= inv; o4.y *= inv; o4.z *= inv; o4.w *= inv;
        *(float4*)(g_att + ((size_t)(b * S + qpos)) * D + h * HD + lane * 4) = o4;
    }
}

// ---------------- launch -----------------------------------------------------
extern "C" void kernel_launch(void* const* d_in, const int* in_sizes, int n_in,
                              void* d_out, int out_size) {
    const float* x  = (const float*)d_in[0];
    const float* g  = (const float*)d_in[1];
    const float* wq = (const float*)d_in[2];
    const float* wk = (const float*)d_in[3];
    const float* wv = (const float*)d_in[4];
    const float* wo = (const float*)d_in[5];
    float* out = (float*)d_out;

    void *p_xn, *p_qp, *p_kp, *p_vp, *p_att;
    cudaGetSymbolAddress(&p_xn,  g_xn);
    cudaGetSymbolAddress(&p_qp,  g_qp);
    cudaGetSymbolAddress(&p_kp,  g_kp);
    cudaGetSymbolAddress(&p_vp,  g_vp);
    cudaGetSymbolAddress(&p_att, g_att);

    const int attn_smem = (QT + 2 * KT) * PSTR * sizeof(float);  // 67584
    cudaFuncSetAttribute(attn_kernel,
                         cudaFuncAttributeMaxDynamicSharedMemorySize, attn_smem);

    rope_table_kernel<<<S, HD / 2>>>();
    rmsnorm_kernel<<<BS, 256>>>(x, g);

    sgemm_kernel<<<dim3((HQ*HD)/128,  BS/128), 256>>>((const float*)p_xn, wq, (float*)p_qp, BS, HQ*HD,  D);
    sgemm_kernel<<<dim3((HKV*HD)/128, BS/128), 256>>>((const float*)p_xn, wk, (float*)p_kp, BS, HKV*HD, D);
    sgemm_kernel<<<dim3((HKV*HD)/128, BS/128), 256>>>((const float*)p_xn, wv, (float*)p_vp, BS, HKV*HD, D);

    rope_q_kernel<<<BS, 256>>>();
    rope_k_kernel<<<BS, 256>>>();
    vtrans_kernel<<<BS, 128>>>();

    attn_kernel<<<dim3(S / QT, B * HQ), 256, attn_smem>>>();

    sgemm_kernel<<<dim3(D/128, BS/128), 256>>>((const float*)p_att, wo, out, BS, D, D);
}